// round 12
// baseline (speedup 1.0000x reference)
#include <cuda_runtime.h>
#include <math.h>

#define BB 64        // batch
#define TT 512       // seq len
#define HH 256       // hidden
#define G4 1024      // 4*H
#define NCLS 20

// Scratch (static device globals — no runtime allocation)
__device__ float g_xz[(size_t)BB * TT * G4];   // 128 MB
__device__ float g_hbuf[2][BB * HH];
__device__ unsigned g_flag2[4][32][32];        // [bgrp][consumer][producer]

// ---------------------------------------------------------------------------
// helpers
// ---------------------------------------------------------------------------
__device__ __forceinline__ unsigned long long ffma2(unsigned long long a,
                                                    unsigned long long b,
                                                    unsigned long long c) {
    unsigned long long d;
    asm("fma.rn.f32x2 %0, %1, %2, %3;" : "=l"(d) : "l"(a), "l"(b), "l"(c));
    return d;
}
__device__ __forceinline__ float sum2(unsigned long long v) {
    float lo, hi;
    asm("mov.b64 {%0, %1}, %2;" : "=f"(lo), "=f"(hi) : "l"(v));
    return lo + hi;
}
__device__ __forceinline__ unsigned ld_acq(const unsigned* p) {
    unsigned v;
    asm volatile("ld.acquire.gpu.global.b32 %0, [%1];" : "=r"(v) : "l"(p));
    return v;
}
__device__ __forceinline__ void st_rel(unsigned* p, unsigned v) {
    asm volatile("st.release.gpu.global.b32 [%0], %1;" :: "l"(p), "r"(v));
}
__device__ __forceinline__ float tanh_ap(float x) {
    float y;
    asm("tanh.approx.f32 %0, %1;" : "=f"(y) : "f"(x));
    return y;
}
__device__ __forceinline__ float sigm_ap(float x) {
    return fmaf(0.5f, tanh_ap(0.5f * x), 0.5f);
}

// ---------------------------------------------------------------------------
// Phase A: xz[b,t,:] = emb[x[b,t]] @ W + bias      (M=32768, K=256, N=1024)
// 128x128 tile, 256 threads, 8x8 micro-tile.   (unchanged)
// ---------------------------------------------------------------------------
__global__ __launch_bounds__(256) void phaseA_kernel(
    const int* __restrict__ x, const float* __restrict__ emb,
    const float* __restrict__ W, const float* __restrict__ bias)
{
    __shared__ float As[16][136];
    __shared__ float Bs[16][136];
    __shared__ int ridx[128];

    const int tid = threadIdx.x;
    const int bx = blockIdx.x;   // 0..7
    const int by = blockIdx.y;   // 0..255

    if (tid < 128) ridx[tid] = x[by * 128 + tid];
    __syncthreads();

    const int tx = tid & 15;
    const int ty = tid >> 4;

    float acc[8][8];
#pragma unroll
    for (int i = 0; i < 8; i++)
#pragma unroll
        for (int j = 0; j < 8; j++) acc[i][j] = 0.f;

    const int ar  = tid >> 1;
    const int akq = (tid & 1) << 3;
    const int bkk = tid >> 4;
    const int bc8 = (tid & 15) << 3;

    for (int k0 = 0; k0 < 256; k0 += 16) {
        {
            const float* ap = emb + (size_t)ridx[ar] * 256 + k0 + akq;
            float4 va = *(const float4*)(ap);
            float4 vb = *(const float4*)(ap + 4);
            As[akq + 0][ar] = va.x; As[akq + 1][ar] = va.y;
            As[akq + 2][ar] = va.z; As[akq + 3][ar] = va.w;
            As[akq + 4][ar] = vb.x; As[akq + 5][ar] = vb.y;
            As[akq + 6][ar] = vb.z; As[akq + 7][ar] = vb.w;
            const float* bp = W + (size_t)(k0 + bkk) * G4 + bx * 128 + bc8;
            *(float4*)&Bs[bkk][bc8]     = *(const float4*)(bp);
            *(float4*)&Bs[bkk][bc8 + 4] = *(const float4*)(bp + 4);
        }
        __syncthreads();
#pragma unroll
        for (int k = 0; k < 16; k++) {
            float a[8], b[8];
            float4 a0 = *(const float4*)&As[k][ty << 3];
            float4 a1 = *(const float4*)&As[k][(ty << 3) + 4];
            float4 b0 = *(const float4*)&Bs[k][tx << 3];
            float4 b1 = *(const float4*)&Bs[k][(tx << 3) + 4];
            a[0]=a0.x; a[1]=a0.y; a[2]=a0.z; a[3]=a0.w;
            a[4]=a1.x; a[5]=a1.y; a[6]=a1.z; a[7]=a1.w;
            b[0]=b0.x; b[1]=b0.y; b[2]=b0.z; b[3]=b0.w;
            b[4]=b1.x; b[5]=b1.y; b[6]=b1.z; b[7]=b1.w;
#pragma unroll
            for (int i = 0; i < 8; i++)
#pragma unroll
                for (int j = 0; j < 8; j++)
                    acc[i][j] = fmaf(a[i], b[j], acc[i][j]);
        }
        __syncthreads();
    }

    const int colbase = bx * 128 + (tx << 3);
    float4 bv0 = *(const float4*)(bias + colbase);
    float4 bv1 = *(const float4*)(bias + colbase + 4);
#pragma unroll
    for (int i = 0; i < 8; i++) {
        int row = by * 128 + (ty << 3) + i;
        float4 o0 = make_float4(acc[i][0] + bv0.x, acc[i][1] + bv0.y,
                                acc[i][2] + bv0.z, acc[i][3] + bv0.w);
        float4 o1 = make_float4(acc[i][4] + bv1.x, acc[i][5] + bv1.y,
                                acc[i][6] + bv1.z, acc[i][7] + bv1.w);
        float* op = g_xz + (size_t)row * G4 + colbase;
        *(float4*)(op)     = o0;
        *(float4*)(op + 4) = o1;
    }
}

// ---------------------------------------------------------------------------
// Phase B: 512 sequential LSTM steps, persistent grid (128 CTAs), PRIVATE
// per-consumer flag rows (no cross-CTA poll contention). CTA (jgrp, bgrp)
// owns 16 batches x 8 hidden cols. 512 threads: quarter q accumulates k in
// [q*64, q*64+64) with FFMA2. Producer publishes 32 flag copies in one warp
// instruction; each consumer polls ONLY its own 128B flag row.
// ---------------------------------------------------------------------------
#define UT_STRIDE 260   // 1040 B rows (16B aligned)
#define SMEM_B ((48 * UT_STRIDE) * 4 + 3 * 128 * 4 * 4)

extern __shared__ float sdyn[];

__global__ __launch_bounds__(512, 1) void phaseB_kernel(const float* __restrict__ U)
{
    float* Ut   = sdyn;                    // [32][260]  U^T slice (resident)
    float* hs   = sdyn + 32 * UT_STRIDE;   // [16][260]  h stage
    float* part = sdyn + 48 * UT_STRIDE;   // [3][128][4] quarter partials

    const int tid  = threadIdx.x;          // 512
    const int jgrp = blockIdx.x;           // 0..31
    const int bgrp = blockIdx.y;           // 0..3

    // Stage U^T once: local col cl = g*8+jl  ->  global col g*256 + jgrp*8 + jl
    for (int i = tid; i < 32 * 256; i += 512) {
        int cl = i >> 8, k = i & 255;
        int g = cl >> 3, jl = cl & 7;
        Ut[cl * UT_STRIDE + k] = U[(size_t)k * G4 + g * HH + jgrp * 8 + jl];
    }
    // zero h stage (h_0 = 0); staging is skipped at t==0
    for (int i = tid; i < 16 * UT_STRIDE; i += 512) hs[i] = 0.f;

    const int quarter = tid >> 7;          // 0..3 : k quarter
    const int cell    = tid & 127;         // (bl, jl)
    const int bl      = cell >> 3;         // 0..15
    const int jl      = cell & 7;          // 0..7
    const int b       = bgrp * 16 + bl;
    const int j       = jgrp * 8 + jl;
    const int kb      = quarter << 6;      // k base (floats)

    const int wid  = tid >> 5;             // 0..15
    const int lane = tid & 31;

    float c = 0.f;
    const float* xzp = g_xz + (size_t)b * TT * G4 + j;

    const ulonglong2* u0 = (const ulonglong2*)(Ut + (0 * 8 + jl) * UT_STRIDE + kb);
    const ulonglong2* u1 = (const ulonglong2*)(Ut + (1 * 8 + jl) * UT_STRIDE + kb);
    const ulonglong2* u2 = (const ulonglong2*)(Ut + (2 * 8 + jl) * UT_STRIDE + kb);
    const ulonglong2* u3 = (const ulonglong2*)(Ut + (3 * 8 + jl) * UT_STRIDE + kb);
    const ulonglong2* hrow = (const ulonglong2*)(hs + bl * UT_STRIDE + kb);

    // my PRIVATE flag row: one 128B line polled only by this CTA
    const unsigned* myflags = &g_flag2[bgrp][jgrp][0];
    // staging assignment: lane-half selects one of this warp's two peers;
    // within a half, lane covers one of the 16 rows of the 16x8 piece.
    const int speer = (lane >> 4) ? (wid + 16) : wid;   // peer CTA index
    const int srow  = lane & 15;                        // row 0..15
    const unsigned* sflag = myflags + speer;            // private word

    __syncthreads();   // Ut + hs ready

    for (int t = 0; t < TT; t++) {
        // prefetch xz for this step (quarter 0 only; issued before any wait)
        float a0 = 0.f, a1 = 0.f, a2 = 0.f, a3 = 0.f;
        if (quarter == 0) {
            const float* xr = xzp + (size_t)t * G4;
            a0 = __ldg(xr + 0 * HH);
            a1 = __ldg(xr + 1 * HH);
            a2 = __ldg(xr + 2 * HH);
            a3 = __ldg(xr + 3 * HH);
        }

        if (t > 0) {
            // parallel detect (private flag words), then parallel fetch
            while (!__all_sync(0xffffffffu, ld_acq(sflag) >= (unsigned)t)) { }
            const float* src = g_hbuf[t & 1] + (bgrp * 16 + srow) * HH + speer * 8;
            float4 v0 = __ldcg((const float4*)(src));
            float4 v1 = __ldcg((const float4*)(src + 4));
            float* dst = hs + srow * UT_STRIDE + speer * 8;
            *(float4*)(dst)     = v0;
            *(float4*)(dst + 4) = v1;
        }
        __syncthreads();

        unsigned long long s0 = 0ull, s1 = 0ull, s2 = 0ull, s3 = 0ull;
#pragma unroll 4
        for (int k4 = 0; k4 < 16; k4++) {
            ulonglong2 hv = hrow[k4];
            ulonglong2 v0 = u0[k4];
            ulonglong2 v1 = u1[k4];
            ulonglong2 v2 = u2[k4];
            ulonglong2 v3 = u3[k4];
            s0 = ffma2(hv.x, v0.x, s0); s0 = ffma2(hv.y, v0.y, s0);
            s1 = ffma2(hv.x, v1.x, s1); s1 = ffma2(hv.y, v1.y, s1);
            s2 = ffma2(hv.x, v2.x, s2); s2 = ffma2(hv.y, v2.y, s2);
            s3 = ffma2(hv.x, v3.x, s3); s3 = ffma2(hv.y, v3.y, s3);
        }
        float p0 = sum2(s0), p1 = sum2(s1), p2 = sum2(s2), p3 = sum2(s3);

        if (quarter != 0) {
            *(float4*)&part[((quarter - 1) * 128 + cell) * 4] =
                make_float4(p0, p1, p2, p3);
            // producers arrive and run ahead to next step's staging
            asm volatile("bar.arrive 2, 512;" ::: "memory");
        } else {
            asm volatile("bar.sync 2, 512;" ::: "memory");
            float4 q1 = *(const float4*)&part[(0 * 128 + cell) * 4];
            float4 q2 = *(const float4*)&part[(1 * 128 + cell) * 4];
            float4 q3 = *(const float4*)&part[(2 * 128 + cell) * 4];
            float z0 = a0 + p0 + q1.x + q2.x + q3.x;
            float z1 = a1 + p1 + q1.y + q2.y + q3.y;
            float z2 = a2 + p2 + q1.z + q2.z + q3.z;
            float z3 = a3 + p3 + q1.w + q2.w + q3.w;
            // gates (order i, f, g, o)
            float ig = sigm_ap(z0);
            float fg = sigm_ap(z1);
            float gg = tanh_ap(z2);
            float og = sigm_ap(z3);
            c = fmaf(fg, c, ig * gg);
            float hn = og * tanh_ap(c);
            __stcg(&g_hbuf[(t + 1) & 1][b * HH + j], hn);
            // quarter-0 barrier: all 128 h stores issued & ordered
            asm volatile("bar.sync 1, 128;" ::: "memory");
            // publish 32 private flag copies in ONE warp instruction
            if (tid < 32)
                st_rel(&g_flag2[bgrp][tid][jgrp], (unsigned)(t + 1));
        }
    }
}

// ---------------------------------------------------------------------------
// Phase C: logits = h_T @ Wd + bd; softmax. One warp per batch row.
// Final h lives in g_hbuf[0] (512 steps -> buf (511+1)&1 == 0).
// ---------------------------------------------------------------------------
__global__ __launch_bounds__(32) void phaseC_kernel(
    const float* __restrict__ Wd, const float* __restrict__ bd,
    float* __restrict__ out)
{
    const int b = blockIdx.x;
    const int lane = threadIdx.x;
    const float* h = g_hbuf[0] + b * HH;

    float v = 0.f;
    if (lane < NCLS) {
#pragma unroll 8
        for (int k = 0; k < HH; k++)
            v = fmaf(h[k], Wd[k * NCLS + lane], v);
        v += bd[lane];
    }
    float m = (lane < NCLS) ? v : -1e30f;
#pragma unroll
    for (int o = 16; o; o >>= 1) m = fmaxf(m, __shfl_xor_sync(0xffffffffu, m, o));
    float e = (lane < NCLS) ? __expf(v - m) : 0.f;
    float s = e;
#pragma unroll
    for (int o = 16; o; o >>= 1) s += __shfl_xor_sync(0xffffffffu, s, o);
    if (lane < NCLS) out[b * NCLS + lane] = e / s;
}

// ---------------------------------------------------------------------------
extern "C" void kernel_launch(void* const* d_in, const int* in_sizes, int n_in,
                              void* d_out, int out_size)
{
    const int*   x    = (const int*)d_in[0];
    const float* emb  = (const float*)d_in[1];
    const float* W    = (const float*)d_in[2];
    const float* U    = (const float*)d_in[3];
    const float* bias = (const float*)d_in[4];
    const float* Wd   = (const float*)d_in[5];
    const float* bd   = (const float*)d_in[6];
    float* out = (float*)d_out;

    static void* flag_ptr = nullptr;
    static bool inited = false;
    if (!inited) {
        cudaGetSymbolAddress(&flag_ptr, g_flag2);
        cudaFuncSetAttribute(phaseB_kernel,
                             cudaFuncAttributeMaxDynamicSharedMemorySize, SMEM_B);
        inited = true;
    }

    // Reset cross-launch flag state (graph-capturable memset node)
    cudaMemsetAsync(flag_ptr, 0, sizeof(unsigned) * 4 * 32 * 32, 0);

    phaseA_kernel<<<dim3(8, 256), 256>>>(x, emb, W, bias);
    phaseB_kernel<<<dim3(32, 4), 512, SMEM_B>>>(U);
    phaseC_kernel<<<BB, 32>>>(Wd, bd, out);
}

// round 13
// speedup vs baseline: 1.9558x; 1.9558x over previous
#include <cuda_runtime.h>
#include <math.h>

#define BB 64        // batch
#define TT 512       // seq len
#define HH 256       // hidden
#define G4 1024      // 4*H
#define NCLS 20

// Scratch (static device globals — no runtime allocation)
__device__ float g_xz[(size_t)BB * TT * G4];   // 128 MB
__device__ float g_hbuf[2][BB * HH];
__device__ unsigned g_flag[4][32 * 32];        // flag (bgrp, jgrp) at [bgrp][jgrp*32]

// ---------------------------------------------------------------------------
// helpers
// ---------------------------------------------------------------------------
__device__ __forceinline__ unsigned long long ffma2(unsigned long long a,
                                                    unsigned long long b,
                                                    unsigned long long c) {
    unsigned long long d;
    asm("fma.rn.f32x2 %0, %1, %2, %3;" : "=l"(d) : "l"(a), "l"(b), "l"(c));
    return d;
}
__device__ __forceinline__ float sum2(unsigned long long v) {
    float lo, hi;
    asm("mov.b64 {%0, %1}, %2;" : "=f"(lo), "=f"(hi) : "l"(v));
    return lo + hi;
}
__device__ __forceinline__ unsigned ld_acq(const unsigned* p) {
    unsigned v;
    asm volatile("ld.acquire.gpu.global.b32 %0, [%1];" : "=r"(v) : "l"(p));
    return v;
}
__device__ __forceinline__ void st_rel(unsigned* p, unsigned v) {
    asm volatile("st.release.gpu.global.b32 [%0], %1;" :: "l"(p), "r"(v));
}
__device__ __forceinline__ float tanh_ap(float x) {
    float y;
    asm("tanh.approx.f32 %0, %1;" : "=f"(y) : "f"(x));
    return y;
}
__device__ __forceinline__ float sigm_ap(float x) {
    return fmaf(0.5f, tanh_ap(0.5f * x), 0.5f);
}

// ---------------------------------------------------------------------------
// Phase A: xz[b,t,:] = emb[x[b,t]] @ W + bias      (M=32768, K=256, N=1024)
// 128x128 tile, 256 threads, 8x8 micro-tile.   (unchanged)
// ---------------------------------------------------------------------------
__global__ __launch_bounds__(256) void phaseA_kernel(
    const int* __restrict__ x, const float* __restrict__ emb,
    const float* __restrict__ W, const float* __restrict__ bias)
{
    __shared__ float As[16][136];
    __shared__ float Bs[16][136];
    __shared__ int ridx[128];

    const int tid = threadIdx.x;
    const int bx = blockIdx.x;   // 0..7
    const int by = blockIdx.y;   // 0..255

    if (tid < 128) ridx[tid] = x[by * 128 + tid];
    __syncthreads();

    const int tx = tid & 15;
    const int ty = tid >> 4;

    float acc[8][8];
#pragma unroll
    for (int i = 0; i < 8; i++)
#pragma unroll
        for (int j = 0; j < 8; j++) acc[i][j] = 0.f;

    const int ar  = tid >> 1;
    const int akq = (tid & 1) << 3;
    const int bkk = tid >> 4;
    const int bc8 = (tid & 15) << 3;

    for (int k0 = 0; k0 < 256; k0 += 16) {
        {
            const float* ap = emb + (size_t)ridx[ar] * 256 + k0 + akq;
            float4 va = *(const float4*)(ap);
            float4 vb = *(const float4*)(ap + 4);
            As[akq + 0][ar] = va.x; As[akq + 1][ar] = va.y;
            As[akq + 2][ar] = va.z; As[akq + 3][ar] = va.w;
            As[akq + 4][ar] = vb.x; As[akq + 5][ar] = vb.y;
            As[akq + 6][ar] = vb.z; As[akq + 7][ar] = vb.w;
            const float* bp = W + (size_t)(k0 + bkk) * G4 + bx * 128 + bc8;
            *(float4*)&Bs[bkk][bc8]     = *(const float4*)(bp);
            *(float4*)&Bs[bkk][bc8 + 4] = *(const float4*)(bp + 4);
        }
        __syncthreads();
#pragma unroll
        for (int k = 0; k < 16; k++) {
            float a[8], b[8];
            float4 a0 = *(const float4*)&As[k][ty << 3];
            float4 a1 = *(const float4*)&As[k][(ty << 3) + 4];
            float4 b0 = *(const float4*)&Bs[k][tx << 3];
            float4 b1 = *(const float4*)&Bs[k][(tx << 3) + 4];
            a[0]=a0.x; a[1]=a0.y; a[2]=a0.z; a[3]=a0.w;
            a[4]=a1.x; a[5]=a1.y; a[6]=a1.z; a[7]=a1.w;
            b[0]=b0.x; b[1]=b0.y; b[2]=b0.z; b[3]=b0.w;
            b[4]=b1.x; b[5]=b1.y; b[6]=b1.z; b[7]=b1.w;
#pragma unroll
            for (int i = 0; i < 8; i++)
#pragma unroll
                for (int j = 0; j < 8; j++)
                    acc[i][j] = fmaf(a[i], b[j], acc[i][j]);
        }
        __syncthreads();
    }

    const int colbase = bx * 128 + (tx << 3);
    float4 bv0 = *(const float4*)(bias + colbase);
    float4 bv1 = *(const float4*)(bias + colbase + 4);
#pragma unroll
    for (int i = 0; i < 8; i++) {
        int row = by * 128 + (ty << 3) + i;
        float4 o0 = make_float4(acc[i][0] + bv0.x, acc[i][1] + bv0.y,
                                acc[i][2] + bv0.z, acc[i][3] + bv0.w);
        float4 o1 = make_float4(acc[i][4] + bv1.x, acc[i][5] + bv1.y,
                                acc[i][6] + bv1.z, acc[i][7] + bv1.w);
        float* op = g_xz + (size_t)row * G4 + colbase;
        *(float4*)(op)     = o0;
        *(float4*)(op + 4) = o1;
    }
}

// ---------------------------------------------------------------------------
// Phase B: 512 LSTM steps, 128 CTAs (32 jgrp x 4 bgrp), Round-5 L2 flags.
// CTA owns 16 batches x 8 hidden cols (32 gate-cols). 256 threads:
//   thread (bblk 0..3, gcblk 0..3, ks 0..15) computes a 4b x 8gc x 16k tile
//   with packed-k FFMA2 — 12 LDS.128 per 64 ffma2 (2.7x fewer LDS than R5).
// k is stored in 16-float blocks padded to 20 (bank-optimal for 16 ksplits).
// 16-way k-split combine via skewed smem scratch, gates by threads 0-127.
// ---------------------------------------------------------------------------
#define KROW 320                     // 16 blocks * 20 floats
#define UT_OFF 0                     // [32][320]
#define HS_OFF (32 * KROW)           // [16][320]
#define PART_OFF (48 * KROW)         // skewed scratch, 8832 floats
#define SMEM_FLOATS (PART_OFF + 8832)
#define SMEM_B (SMEM_FLOATS * 4)

extern __shared__ float sdyn[];

__global__ __launch_bounds__(256, 1) void phaseB_kernel(const float* __restrict__ U)
{
    float* Ut   = sdyn + UT_OFF;
    float* hs   = sdyn + HS_OFF;
    float* part = sdyn + PART_OFF;

    const int tid  = threadIdx.x;      // 256
    const int jgrp = blockIdx.x;       // 0..31
    const int bgrp = blockIdx.y;       // 0..3

    // Stage U slice: Ut[gc][k] (k block-padded), gc = g*8+jl
    for (int i = tid; i < 32 * 256; i += 256) {
        int gc = i >> 8, k = i & 255;
        int g = gc >> 3, jl = gc & 7;
        Ut[gc * KROW + (k >> 4) * 20 + (k & 15)] =
            U[(size_t)k * G4 + g * HH + jgrp * 8 + jl];
    }
    // zero h stage (h_0 = 0; staging skipped at t==0)
    for (int i = tid; i < 16 * KROW; i += 256) hs[i] = 0.f;

    const int ks    = tid & 15;        // k split 0..15 (16 k each)
    const int gcblk = (tid >> 4) & 3;  // 2 hidden cols
    const int bblk  = tid >> 6;        // 4 batches

    const int wid  = tid >> 5;         // 0..7
    const int lane = tid & 31;

    // compute pointers (k offset ks*20; iter advances by 4 floats = 1 u2)
    const ulonglong2* hp0 = (const ulonglong2*)(hs + (bblk * 4 + 0) * KROW + ks * 20);
    const ulonglong2* hp1 = (const ulonglong2*)(hs + (bblk * 4 + 1) * KROW + ks * 20);
    const ulonglong2* hp2 = (const ulonglong2*)(hs + (bblk * 4 + 2) * KROW + ks * 20);
    const ulonglong2* hp3 = (const ulonglong2*)(hs + (bblk * 4 + 3) * KROW + ks * 20);
    const ulonglong2* up[8];
#pragma unroll
    for (int g = 0; g < 4; g++)
#pragma unroll
        for (int jp = 0; jp < 2; jp++)
            up[g * 2 + jp] = (const ulonglong2*)
                (Ut + (g * 8 + gcblk * 2 + jp) * KROW + ks * 20);

    // staging: warp w covers peers {w, w+8, w+16, w+24}; lane -> peer + 2 rows
    const int speer = ((lane >> 3) << 3) + wid;    // (lane/8)*8 + wid
    const int srow  = (lane & 7) * 2;
    unsigned* flags = &g_flag[bgrp][0];
    const unsigned* sflag = flags + speer * 32;

    // gate-thread params (tid < 128): (bl, jl)
    const int bl = tid >> 3;
    const int jl = tid & 7;
    const int b  = bgrp * 16 + bl;
    const int j  = jgrp * 8 + jl;
    float c = 0.f;
    const float* xzp = g_xz + (size_t)b * TT * G4 + j;

    __syncthreads();   // Ut + hs ready

    for (int t = 0; t < TT; t++) {
        // xz prefetch (gate threads only; issued before any wait)
        float a0 = 0.f, a1 = 0.f, a2 = 0.f, a3 = 0.f;
        if (tid < 128) {
            const float* xr = xzp + (size_t)t * G4;
            a0 = __ldg(xr + 0 * HH);
            a1 = __ldg(xr + 1 * HH);
            a2 = __ldg(xr + 2 * HH);
            a3 = __ldg(xr + 3 * HH);
        }

        if (t > 0) {
            // parallel detect of 4 peers/warp, then fetch 2 rows x 8 floats
            while (!__all_sync(0xffffffffu, ld_acq(sflag) >= (unsigned)t)) { }
            const float* src = g_hbuf[t & 1] + (bgrp * 16 + srow) * HH + speer * 8;
            float4 v0 = __ldcg((const float4*)(src));
            float4 v1 = __ldcg((const float4*)(src + 4));
            float4 v2 = __ldcg((const float4*)(src + HH));
            float4 v3 = __ldcg((const float4*)(src + HH + 4));
            float* dst = hs + srow * KROW + (speer >> 1) * 20 + (speer & 1) * 8;
            *(float4*)(dst)            = v0;
            *(float4*)(dst + 4)        = v1;
            *(float4*)(dst + KROW)     = v2;
            *(float4*)(dst + KROW + 4) = v3;
        }
        __syncthreads();   // A: h staged

        // ---- main tile: 4b x 8gc x 16k, packed-k accumulators ----
        unsigned long long acc[32];
#pragma unroll
        for (int q = 0; q < 32; q++) acc[q] = 0ull;

#pragma unroll
        for (int iter = 0; iter < 4; iter++) {
            ulonglong2 h0 = hp0[iter];
            ulonglong2 h1 = hp1[iter];
            ulonglong2 h2 = hp2[iter];
            ulonglong2 h3 = hp3[iter];
#pragma unroll
            for (int t8 = 0; t8 < 8; t8++) {
                ulonglong2 uv = up[t8][iter];
                acc[0 * 8 + t8] = ffma2(h0.x, uv.x, acc[0 * 8 + t8]);
                acc[0 * 8 + t8] = ffma2(h0.y, uv.y, acc[0 * 8 + t8]);
                acc[1 * 8 + t8] = ffma2(h1.x, uv.x, acc[1 * 8 + t8]);
                acc[1 * 8 + t8] = ffma2(h1.y, uv.y, acc[1 * 8 + t8]);
                acc[2 * 8 + t8] = ffma2(h2.x, uv.x, acc[2 * 8 + t8]);
                acc[2 * 8 + t8] = ffma2(h2.y, uv.y, acc[2 * 8 + t8]);
                acc[3 * 8 + t8] = ffma2(h3.x, uv.x, acc[3 * 8 + t8]);
                acc[3 * 8 + t8] = ffma2(h3.y, uv.y, acc[3 * 8 + t8]);
            }
        }

        // fold + write skewed partials: addr = cell*17 + b_local*8 + ks
#pragma unroll
        for (int i = 0; i < 4; i++) {
            int bloc = bblk * 4 + i;
            int base = (bloc * 32 + gcblk * 2) * 17 + bloc * 8 + ks;
#pragma unroll
            for (int t8 = 0; t8 < 8; t8++) {
                int g = t8 >> 1, jp = t8 & 1;
                part[base + g * 136 + jp * 17] = sum2(acc[i * 8 + t8]);
            }
        }
        __syncthreads();   // B: partials visible

        if (tid < 128) {
            float z[4];
#pragma unroll
            for (int g = 0; g < 4; g++) {
                int base = (bl * 32 + g * 8 + jl) * 17 + bl * 8;
                float s0 = part[base + 0] + part[base + 1];
                float s1 = part[base + 2] + part[base + 3];
                float s2 = part[base + 4] + part[base + 5];
                float s3 = part[base + 6] + part[base + 7];
                float s4 = part[base + 8] + part[base + 9];
                float s5 = part[base + 10] + part[base + 11];
                float s6 = part[base + 12] + part[base + 13];
                float s7 = part[base + 14] + part[base + 15];
                z[g] = ((s0 + s1) + (s2 + s3)) + ((s4 + s5) + (s6 + s7));
            }
            float z0 = a0 + z[0];
            float z1 = a1 + z[1];
            float z2 = a2 + z[2];
            float z3 = a3 + z[3];
            // gates (order i, f, g, o)
            float ig = sigm_ap(z0);
            float fg = sigm_ap(z1);
            float gg = tanh_ap(z2);
            float og = sigm_ap(z3);
            c = fmaf(fg, c, ig * gg);
            float hn = og * tanh_ap(c);
            __stcg(&g_hbuf[(t + 1) & 1][b * HH + j], hn);
            asm volatile("bar.sync 1, 128;" ::: "memory");
            if (tid == 0) st_rel(flags + jgrp * 32, (unsigned)(t + 1));
        }
    }
}

// ---------------------------------------------------------------------------
// Phase C: logits = h_T @ Wd + bd; softmax. One warp per batch row.
// Final h lives in g_hbuf[0] (512 steps -> buf (511+1)&1 == 0).
// ---------------------------------------------------------------------------
__global__ __launch_bounds__(32) void phaseC_kernel(
    const float* __restrict__ Wd, const float* __restrict__ bd,
    float* __restrict__ out)
{
    const int b = blockIdx.x;
    const int lane = threadIdx.x;
    const float* h = g_hbuf[0] + b * HH;

    float v = 0.f;
    if (lane < NCLS) {
#pragma unroll 8
        for (int k = 0; k < HH; k++)
            v = fmaf(h[k], Wd[k * NCLS + lane], v);
        v += bd[lane];
    }
    float m = (lane < NCLS) ? v : -1e30f;
#pragma unroll
    for (int o = 16; o; o >>= 1) m = fmaxf(m, __shfl_xor_sync(0xffffffffu, m, o));
    float e = (lane < NCLS) ? __expf(v - m) : 0.f;
    float s = e;
#pragma unroll
    for (int o = 16; o; o >>= 1) s += __shfl_xor_sync(0xffffffffu, s, o);
    if (lane < NCLS) out[b * NCLS + lane] = e / s;
}

// ---------------------------------------------------------------------------
extern "C" void kernel_launch(void* const* d_in, const int* in_sizes, int n_in,
                              void* d_out, int out_size)
{
    const int*   x    = (const int*)d_in[0];
    const float* emb  = (const float*)d_in[1];
    const float* W    = (const float*)d_in[2];
    const float* U    = (const float*)d_in[3];
    const float* bias = (const float*)d_in[4];
    const float* Wd   = (const float*)d_in[5];
    const float* bd   = (const float*)d_in[6];
    float* out = (float*)d_out;

    static void* flag_ptr = nullptr;
    static bool inited = false;
    if (!inited) {
        cudaGetSymbolAddress(&flag_ptr, g_flag);
        cudaFuncSetAttribute(phaseB_kernel,
                             cudaFuncAttributeMaxDynamicSharedMemorySize, SMEM_B);
        inited = true;
    }

    // Reset cross-launch flag state (graph-capturable memset node)
    cudaMemsetAsync(flag_ptr, 0, sizeof(unsigned) * 4 * 32 * 32, 0);

    phaseA_kernel<<<dim3(8, 256), 256>>>(x, emb, W, bias);
    phaseB_kernel<<<dim3(32, 4), 256, SMEM_B>>>(U);
    phaseC_kernel<<<BB, 32>>>(Wd, bd, out);
}

// round 14
// speedup vs baseline: 2.4965x; 1.2765x over previous
#include <cuda_runtime.h>
#include <math.h>

#define BB 64        // batch
#define TT 512       // seq len
#define HH 256       // hidden
#define G4 1024      // 4*H
#define NCLS 20

// Scratch (static device globals — no runtime allocation)
__device__ float g_xz[(size_t)BB * TT * G4];   // 128 MB
__device__ float g_hbuf[2][BB * HH];
__device__ unsigned g_flag2[16][8][32];        // [bgrp][producer jgrp][line pad]

// ---------------------------------------------------------------------------
// helpers
// ---------------------------------------------------------------------------
__device__ __forceinline__ unsigned long long ffma2(unsigned long long a,
                                                    unsigned long long b,
                                                    unsigned long long c) {
    unsigned long long d;
    asm("fma.rn.f32x2 %0, %1, %2, %3;" : "=l"(d) : "l"(a), "l"(b), "l"(c));
    return d;
}
__device__ __forceinline__ float sum2(unsigned long long v) {
    float lo, hi;
    asm("mov.b64 {%0, %1}, %2;" : "=f"(lo), "=f"(hi) : "l"(v));
    return lo + hi;
}
__device__ __forceinline__ unsigned ld_acq(const unsigned* p) {
    unsigned v;
    asm volatile("ld.acquire.gpu.global.b32 %0, [%1];" : "=r"(v) : "l"(p));
    return v;
}
__device__ __forceinline__ void st_rel(unsigned* p, unsigned v) {
    asm volatile("st.release.gpu.global.b32 [%0], %1;" :: "l"(p), "r"(v));
}
__device__ __forceinline__ float tanh_ap(float x) {
    float y;
    asm("tanh.approx.f32 %0, %1;" : "=f"(y) : "f"(x));
    return y;
}
__device__ __forceinline__ float sigm_ap(float x) {
    return fmaf(0.5f, tanh_ap(0.5f * x), 0.5f);
}

// ---------------------------------------------------------------------------
// Phase A: xz[b,t,:] = emb[x[b,t]] @ W + bias      (M=32768, K=256, N=1024)
// 128x128 tile, 256 threads, 8x8 micro-tile.   (unchanged)
// ---------------------------------------------------------------------------
__global__ __launch_bounds__(256) void phaseA_kernel(
    const int* __restrict__ x, const float* __restrict__ emb,
    const float* __restrict__ W, const float* __restrict__ bias)
{
    __shared__ float As[16][136];
    __shared__ float Bs[16][136];
    __shared__ int ridx[128];

    const int tid = threadIdx.x;
    const int bx = blockIdx.x;   // 0..7
    const int by = blockIdx.y;   // 0..255

    if (tid < 128) ridx[tid] = x[by * 128 + tid];
    __syncthreads();

    const int tx = tid & 15;
    const int ty = tid >> 4;

    float acc[8][8];
#pragma unroll
    for (int i = 0; i < 8; i++)
#pragma unroll
        for (int j = 0; j < 8; j++) acc[i][j] = 0.f;

    const int ar  = tid >> 1;
    const int akq = (tid & 1) << 3;
    const int bkk = tid >> 4;
    const int bc8 = (tid & 15) << 3;

    for (int k0 = 0; k0 < 256; k0 += 16) {
        {
            const float* ap = emb + (size_t)ridx[ar] * 256 + k0 + akq;
            float4 va = *(const float4*)(ap);
            float4 vb = *(const float4*)(ap + 4);
            As[akq + 0][ar] = va.x; As[akq + 1][ar] = va.y;
            As[akq + 2][ar] = va.z; As[akq + 3][ar] = va.w;
            As[akq + 4][ar] = vb.x; As[akq + 5][ar] = vb.y;
            As[akq + 6][ar] = vb.z; As[akq + 7][ar] = vb.w;
            const float* bp = W + (size_t)(k0 + bkk) * G4 + bx * 128 + bc8;
            *(float4*)&Bs[bkk][bc8]     = *(const float4*)(bp);
            *(float4*)&Bs[bkk][bc8 + 4] = *(const float4*)(bp + 4);
        }
        __syncthreads();
#pragma unroll
        for (int k = 0; k < 16; k++) {
            float a[8], b[8];
            float4 a0 = *(const float4*)&As[k][ty << 3];
            float4 a1 = *(const float4*)&As[k][(ty << 3) + 4];
            float4 b0 = *(const float4*)&Bs[k][tx << 3];
            float4 b1 = *(const float4*)&Bs[k][(tx << 3) + 4];
            a[0]=a0.x; a[1]=a0.y; a[2]=a0.z; a[3]=a0.w;
            a[4]=a1.x; a[5]=a1.y; a[6]=a1.z; a[7]=a1.w;
            b[0]=b0.x; b[1]=b0.y; b[2]=b0.z; b[3]=b0.w;
            b[4]=b1.x; b[5]=b1.y; b[6]=b1.z; b[7]=b1.w;
#pragma unroll
            for (int i = 0; i < 8; i++)
#pragma unroll
                for (int j = 0; j < 8; j++)
                    acc[i][j] = fmaf(a[i], b[j], acc[i][j]);
        }
        __syncthreads();
    }

    const int colbase = bx * 128 + (tx << 3);
    float4 bv0 = *(const float4*)(bias + colbase);
    float4 bv1 = *(const float4*)(bias + colbase + 4);
#pragma unroll
    for (int i = 0; i < 8; i++) {
        int row = by * 128 + (ty << 3) + i;
        float4 o0 = make_float4(acc[i][0] + bv0.x, acc[i][1] + bv0.y,
                                acc[i][2] + bv0.z, acc[i][3] + bv0.w);
        float4 o1 = make_float4(acc[i][4] + bv1.x, acc[i][5] + bv1.y,
                                acc[i][6] + bv1.z, acc[i][7] + bv1.w);
        float* op = g_xz + (size_t)row * G4 + colbase;
        *(float4*)(op)     = o0;
        *(float4*)(op + 4) = o1;
    }
}

// ---------------------------------------------------------------------------
// Phase B: 512 LSTM steps, 128 CTAs = 8 jgrp (col groups) x 16 bgrp (4
// batches). EXCHANGE WIDTH 8: each CTA owns 4 batches x 32 hidden cols
// (128 gate-cols, U slice 160KB smem, block-padded k). Per step a CTA waits
// on only 8 producers; warp w polls producer w's private flag line with ONE
// broadcast load and fetches its 512B piece (4 clean 128B lines).
// 256 threads = 16 gcblk x 16 ks; thread tile 4b x 8gc x 16k (FFMA2).
// 16-way k-split combine via skewed smem scratch; gates by threads 0-127.
// ---------------------------------------------------------------------------
#define KROW 320                     // 16 blocks * 20 floats
#define UT_OFF 0                     // [128][320]
#define HS_OFF (128 * KROW)          // [4][320]
#define PART_OFF (132 * KROW)        // skewed scratch
#define SMEM_FLOATS (PART_OFF + 8736)
#define SMEM_B (SMEM_FLOATS * 4)

extern __shared__ float sdyn[];

__global__ __launch_bounds__(256, 1) void phaseB_kernel(const float* __restrict__ U)
{
    float* Ut   = sdyn + UT_OFF;
    float* hs   = sdyn + HS_OFF;
    float* part = sdyn + PART_OFF;

    const int tid  = threadIdx.x;      // 256
    const int jgrp = blockIdx.x;       // 0..7   (col group: 32 hidden cols)
    const int bgrp = blockIdx.y;       // 0..15  (4 batches)

    // Stage U slice: gc = g*32 + jj -> global col g*256 + jgrp*32 + jj
    for (int i = tid; i < 128 * 256; i += 256) {
        int gc = i >> 8, k = i & 255;
        int g = gc >> 5, jj2 = gc & 31;
        Ut[gc * KROW + (k >> 4) * 20 + (k & 15)] =
            U[(size_t)k * G4 + g * HH + jgrp * 32 + jj2];
    }
    // zero h stage (h_0 = 0; staging skipped at t==0)
    for (int i = tid; i < 4 * KROW; i += 256) hs[i] = 0.f;

    const int ks    = tid & 15;        // k split 0..15 (16 k each)
    const int gcblk = tid >> 4;        // 0..15 (8 gate-cols each)

    const int wid  = tid >> 5;         // 0..7
    const int lane = tid & 31;

    // compute pointers (k offset ks*20; iter advances 4 floats = 1 u2)
    const ulonglong2* hp0 = (const ulonglong2*)(hs + 0 * KROW + ks * 20);
    const ulonglong2* hp1 = (const ulonglong2*)(hs + 1 * KROW + ks * 20);
    const ulonglong2* hp2 = (const ulonglong2*)(hs + 2 * KROW + ks * 20);
    const ulonglong2* hp3 = (const ulonglong2*)(hs + 3 * KROW + ks * 20);
    const ulonglong2* up[8];
#pragma unroll
    for (int t8 = 0; t8 < 8; t8++)
        up[t8] = (const ulonglong2*)(Ut + (gcblk * 8 + t8) * KROW + ks * 20);

    // staging: warp w handles producer w entirely (one flag, one 512B piece)
    const unsigned* sflag = &g_flag2[bgrp][wid][0];
    const int srow = lane >> 3;               // batch row 0..3
    const int scol = (lane & 7) * 4;          // col offset 0..28
    const int sj   = wid * 32 + scol;         // hidden col
    float* sdst = hs + srow * KROW + (sj >> 4) * 20 + (sj & 15);

    // gate-thread params (tid < 128): (bl 0..3, jj 0..31)
    const int bl = tid >> 5;
    const int jl = tid & 31;
    const int b  = bgrp * 4 + bl;
    const int j  = jgrp * 32 + jl;
    float c = 0.f;
    const float* xzp = g_xz + (size_t)b * TT * G4 + j;

    __syncthreads();   // Ut + hs ready

    for (int t = 0; t < TT; t++) {
        // xz prefetch (gate threads only; issued before any wait)
        float a0 = 0.f, a1 = 0.f, a2 = 0.f, a3 = 0.f;
        if (tid < 128) {
            const float* xr = xzp + (size_t)t * G4;
            a0 = __ldg(xr + 0 * HH);
            a1 = __ldg(xr + 1 * HH);
            a2 = __ldg(xr + 2 * HH);
            a3 = __ldg(xr + 3 * HH);
        }

        if (t > 0) {
            // ONE broadcast flag poll per warp, then fetch 512B piece
            while (ld_acq(sflag) < (unsigned)t) { }
            const float* src =
                g_hbuf[t & 1] + (bgrp * 4 + srow) * HH + wid * 32 + scol;
            float4 v = __ldcg((const float4*)(src));
            *(float4*)sdst = v;
        }
        __syncthreads();   // A: h staged

        // ---- main tile: 4b x 8gc x 16k, packed-k accumulators ----
        unsigned long long acc[32];
#pragma unroll
        for (int q = 0; q < 32; q++) acc[q] = 0ull;

#pragma unroll
        for (int iter = 0; iter < 4; iter++) {
            ulonglong2 h0 = hp0[iter];
            ulonglong2 h1 = hp1[iter];
            ulonglong2 h2 = hp2[iter];
            ulonglong2 h3 = hp3[iter];
#pragma unroll
            for (int t8 = 0; t8 < 8; t8++) {
                ulonglong2 uv = up[t8][iter];
                acc[0 * 8 + t8] = ffma2(h0.x, uv.x, acc[0 * 8 + t8]);
                acc[0 * 8 + t8] = ffma2(h0.y, uv.y, acc[0 * 8 + t8]);
                acc[1 * 8 + t8] = ffma2(h1.x, uv.x, acc[1 * 8 + t8]);
                acc[1 * 8 + t8] = ffma2(h1.y, uv.y, acc[1 * 8 + t8]);
                acc[2 * 8 + t8] = ffma2(h2.x, uv.x, acc[2 * 8 + t8]);
                acc[2 * 8 + t8] = ffma2(h2.y, uv.y, acc[2 * 8 + t8]);
                acc[3 * 8 + t8] = ffma2(h3.x, uv.x, acc[3 * 8 + t8]);
                acc[3 * 8 + t8] = ffma2(h3.y, uv.y, acc[3 * 8 + t8]);
            }
        }

        // fold + write skewed partials: addr = (b*128 + gc)*17 + b*8 + ks
#pragma unroll
        for (int i = 0; i < 4; i++) {
            int base = (i * 128 + gcblk * 8) * 17 + i * 8 + ks;
#pragma unroll
            for (int t8 = 0; t8 < 8; t8++)
                part[base + t8 * 17] = sum2(acc[i * 8 + t8]);
        }
        __syncthreads();   // B: partials visible

        if (tid < 128) {
            float z[4];
#pragma unroll
            for (int g = 0; g < 4; g++) {
                int base = (bl * 128 + g * 32 + jl) * 17 + bl * 8;
                float s0 = part[base + 0] + part[base + 1];
                float s1 = part[base + 2] + part[base + 3];
                float s2 = part[base + 4] + part[base + 5];
                float s3 = part[base + 6] + part[base + 7];
                float s4 = part[base + 8] + part[base + 9];
                float s5 = part[base + 10] + part[base + 11];
                float s6 = part[base + 12] + part[base + 13];
                float s7 = part[base + 14] + part[base + 15];
                z[g] = ((s0 + s1) + (s2 + s3)) + ((s4 + s5) + (s6 + s7));
            }
            float z0 = a0 + z[0];
            float z1 = a1 + z[1];
            float z2 = a2 + z[2];
            float z3 = a3 + z[3];
            // gates (order i, f, g, o)
            float ig = sigm_ap(z0);
            float fg = sigm_ap(z1);
            float gg = tanh_ap(z2);
            float og = sigm_ap(z3);
            c = fmaf(fg, c, ig * gg);
            float hn = og * tanh_ap(c);
            __stcg(&g_hbuf[(t + 1) & 1][b * HH + j], hn);
            asm volatile("bar.sync 1, 128;" ::: "memory");
            if (tid == 0) st_rel(&g_flag2[bgrp][jgrp][0], (unsigned)(t + 1));
        }
    }
}

// ---------------------------------------------------------------------------
// Phase C: logits = h_T @ Wd + bd; softmax. One warp per batch row.
// Final h lives in g_hbuf[0] (512 steps -> buf (511+1)&1 == 0).
// ---------------------------------------------------------------------------
__global__ __launch_bounds__(32) void phaseC_kernel(
    const float* __restrict__ Wd, const float* __restrict__ bd,
    float* __restrict__ out)
{
    const int b = blockIdx.x;
    const int lane = threadIdx.x;
    const float* h = g_hbuf[0] + b * HH;

    float v = 0.f;
    if (lane < NCLS) {
#pragma unroll 8
        for (int k = 0; k < HH; k++)
            v = fmaf(h[k], Wd[k * NCLS + lane], v);
        v += bd[lane];
    }
    float m = (lane < NCLS) ? v : -1e30f;
#pragma unroll
    for (int o = 16; o; o >>= 1) m = fmaxf(m, __shfl_xor_sync(0xffffffffu, m, o));
    float e = (lane < NCLS) ? __expf(v - m) : 0.f;
    float s = e;
#pragma unroll
    for (int o = 16; o; o >>= 1) s += __shfl_xor_sync(0xffffffffu, s, o);
    if (lane < NCLS) out[b * NCLS + lane] = e / s;
}

// ---------------------------------------------------------------------------
extern "C" void kernel_launch(void* const* d_in, const int* in_sizes, int n_in,
                              void* d_out, int out_size)
{
    const int*   x    = (const int*)d_in[0];
    const float* emb  = (const float*)d_in[1];
    const float* W    = (const float*)d_in[2];
    const float* U    = (const float*)d_in[3];
    const float* bias = (const float*)d_in[4];
    const float* Wd   = (const float*)d_in[5];
    const float* bd   = (const float*)d_in[6];
    float* out = (float*)d_out;

    static void* flag_ptr = nullptr;
    static bool inited = false;
    if (!inited) {
        cudaGetSymbolAddress(&flag_ptr, g_flag2);
        cudaFuncSetAttribute(phaseB_kernel,
                             cudaFuncAttributeMaxDynamicSharedMemorySize, SMEM_B);
        inited = true;
    }

    // Reset cross-launch flag state (graph-capturable memset node)
    cudaMemsetAsync(flag_ptr, 0, sizeof(unsigned) * 16 * 8 * 32, 0);

    phaseA_kernel<<<dim3(8, 256), 256>>>(x, emb, W, bias);
    phaseB_kernel<<<dim3(8, 16), 256, SMEM_B>>>(U);
    phaseC_kernel<<<BB, 32>>>(Wd, bd, out);
}

// round 15
// speedup vs baseline: 2.6966x; 1.0801x over previous
#include <cuda_runtime.h>
#include <math.h>

#define BB 64        // batch
#define TT 512       // seq len
#define HH 256       // hidden
#define G4 1024      // 4*H
#define NCLS 20

// Scratch (static device globals — no runtime allocation)
__device__ float g_xz[(size_t)BB * TT * G4];   // 128 MB
__device__ float g_hbuf[2][BB * HH];
__device__ unsigned g_flag2[16][8][32];        // [bgrp][producer jgrp][line pad]

// ---------------------------------------------------------------------------
// helpers
// ---------------------------------------------------------------------------
__device__ __forceinline__ unsigned long long ffma2(unsigned long long a,
                                                    unsigned long long b,
                                                    unsigned long long c) {
    unsigned long long d;
    asm("fma.rn.f32x2 %0, %1, %2, %3;" : "=l"(d) : "l"(a), "l"(b), "l"(c));
    return d;
}
__device__ __forceinline__ unsigned long long pack2(float lo, float hi) {
    unsigned long long d;
    asm("mov.b64 %0, {%1, %2};" : "=l"(d) : "f"(lo), "f"(hi));
    return d;
}
__device__ __forceinline__ float sum2(unsigned long long v) {
    float lo, hi;
    asm("mov.b64 {%0, %1}, %2;" : "=f"(lo), "=f"(hi) : "l"(v));
    return lo + hi;
}
__device__ __forceinline__ unsigned ld_acq(const unsigned* p) {
    unsigned v;
    asm volatile("ld.acquire.gpu.global.b32 %0, [%1];" : "=r"(v) : "l"(p));
    return v;
}
__device__ __forceinline__ void st_rel(unsigned* p, unsigned v) {
    asm volatile("st.release.gpu.global.b32 [%0], %1;" :: "l"(p), "r"(v));
}
__device__ __forceinline__ float tanh_ap(float x) {
    float y;
    asm("tanh.approx.f32 %0, %1;" : "=f"(y) : "f"(x));
    return y;
}
__device__ __forceinline__ float sigm_ap(float x) {
    return fmaf(0.5f, tanh_ap(0.5f * x), 0.5f);
}

// ---------------------------------------------------------------------------
// Phase A: xz[b,t,:] = emb[x[b,t]] @ W + bias      (M=32768, K=256, N=1024)
// 128x128 tile, 256 threads, 8x8 micro-tile.   (unchanged)
// ---------------------------------------------------------------------------
__global__ __launch_bounds__(256) void phaseA_kernel(
    const int* __restrict__ x, const float* __restrict__ emb,
    const float* __restrict__ W, const float* __restrict__ bias)
{
    __shared__ float As[16][136];
    __shared__ float Bs[16][136];
    __shared__ int ridx[128];

    const int tid = threadIdx.x;
    const int bx = blockIdx.x;   // 0..7
    const int by = blockIdx.y;   // 0..255

    if (tid < 128) ridx[tid] = x[by * 128 + tid];
    __syncthreads();

    const int tx = tid & 15;
    const int ty = tid >> 4;

    float acc[8][8];
#pragma unroll
    for (int i = 0; i < 8; i++)
#pragma unroll
        for (int j = 0; j < 8; j++) acc[i][j] = 0.f;

    const int ar  = tid >> 1;
    const int akq = (tid & 1) << 3;
    const int bkk = tid >> 4;
    const int bc8 = (tid & 15) << 3;

    for (int k0 = 0; k0 < 256; k0 += 16) {
        {
            const float* ap = emb + (size_t)ridx[ar] * 256 + k0 + akq;
            float4 va = *(const float4*)(ap);
            float4 vb = *(const float4*)(ap + 4);
            As[akq + 0][ar] = va.x; As[akq + 1][ar] = va.y;
            As[akq + 2][ar] = va.z; As[akq + 3][ar] = va.w;
            As[akq + 4][ar] = vb.x; As[akq + 5][ar] = vb.y;
            As[akq + 6][ar] = vb.z; As[akq + 7][ar] = vb.w;
            const float* bp = W + (size_t)(k0 + bkk) * G4 + bx * 128 + bc8;
            *(float4*)&Bs[bkk][bc8]     = *(const float4*)(bp);
            *(float4*)&Bs[bkk][bc8 + 4] = *(const float4*)(bp + 4);
        }
        __syncthreads();
#pragma unroll
        for (int k = 0; k < 16; k++) {
            float a[8], b[8];
            float4 a0 = *(const float4*)&As[k][ty << 3];
            float4 a1 = *(const float4*)&As[k][(ty << 3) + 4];
            float4 b0 = *(const float4*)&Bs[k][tx << 3];
            float4 b1 = *(const float4*)&Bs[k][(tx << 3) + 4];
            a[0]=a0.x; a[1]=a0.y; a[2]=a0.z; a[3]=a0.w;
            a[4]=a1.x; a[5]=a1.y; a[6]=a1.z; a[7]=a1.w;
            b[0]=b0.x; b[1]=b0.y; b[2]=b0.z; b[3]=b0.w;
            b[4]=b1.x; b[5]=b1.y; b[6]=b1.z; b[7]=b1.w;
#pragma unroll
            for (int i = 0; i < 8; i++)
#pragma unroll
                for (int j = 0; j < 8; j++)
                    acc[i][j] = fmaf(a[i], b[j], acc[i][j]);
        }
        __syncthreads();
    }

    const int colbase = bx * 128 + (tx << 3);
    float4 bv0 = *(const float4*)(bias + colbase);
    float4 bv1 = *(const float4*)(bias + colbase + 4);
#pragma unroll
    for (int i = 0; i < 8; i++) {
        int row = by * 128 + (ty << 3) + i;
        float4 o0 = make_float4(acc[i][0] + bv0.x, acc[i][1] + bv0.y,
                                acc[i][2] + bv0.z, acc[i][3] + bv0.w);
        float4 o1 = make_float4(acc[i][4] + bv1.x, acc[i][5] + bv1.y,
                                acc[i][6] + bv1.z, acc[i][7] + bv1.w);
        float* op = g_xz + (size_t)row * G4 + colbase;
        *(float4*)(op)     = o0;
        *(float4*)(op + 4) = o1;
    }
}

// ---------------------------------------------------------------------------
// Phase B: 512 LSTM steps, 128 CTAs = 8 jgrp x 16 bgrp (R14 topology).
// NEW: U lives in REGISTERS — each thread permanently holds its 8gc x 16k
// U tile as 64 packed k-pair ulls (loaded once at init, vectorized LDG).
// Hot loop reads ONLY h from smem: 16 LDS.128/thread/step (2 phases each)
// vs R14's 48 — crossbar ~1800 -> ~300 cyc/step; FMA pipe becomes floor.
// Staging / flags / skewed combine / gates identical to R14.
// ---------------------------------------------------------------------------
#define KROW 320                     // 16 k-blocks * 20 floats (bank-optimal)
#define HS_OFF 0                     // [4][320]
#define PART_OFF (4 * KROW)          // skewed scratch
#define SMEM_FLOATS (PART_OFF + 8736)
#define SMEM_B (SMEM_FLOATS * 4)

extern __shared__ float sdyn[];

__global__ __launch_bounds__(256, 1) void phaseB_kernel(const float* __restrict__ U)
{
    float* hs   = sdyn + HS_OFF;
    float* part = sdyn + PART_OFF;

    const int tid  = threadIdx.x;      // 256
    const int jgrp = blockIdx.x;       // 0..7   (col group: 32 hidden cols)
    const int bgrp = blockIdx.y;       // 0..15  (4 batches)

    const int ks    = tid & 15;        // k split 0..15 (16 k each)
    const int gcblk = tid >> 4;        // 0..15 (8 gate-cols each)

    const int wid  = tid >> 5;         // 0..7
    const int lane = tid & 31;

    // ---- load this thread's U tile into registers (one-time) ----
    // gc = gcblk*8 + t8 stays within one 32-block (gcblk*8 mod 32 <= 24),
    // so g is fixed and the 8 global cols are consecutive.
    unsigned long long ureg[8][8];     // [t8][k-pair p], k = ks*16 + 2p
    {
        const int gc0  = gcblk * 8;
        const int colb = (gc0 >> 5) * HH + jgrp * 32 + (gc0 & 31);
#pragma unroll
        for (int p = 0; p < 8; p++) {
            const float* r0 = U + (size_t)(ks * 16 + 2 * p) * G4 + colb;
            const float* r1 = r0 + G4;
            float4 a0 = *(const float4*)(r0);
            float4 a1 = *(const float4*)(r0 + 4);
            float4 b0 = *(const float4*)(r1);
            float4 b1 = *(const float4*)(r1 + 4);
            ureg[0][p] = pack2(a0.x, b0.x);
            ureg[1][p] = pack2(a0.y, b0.y);
            ureg[2][p] = pack2(a0.z, b0.z);
            ureg[3][p] = pack2(a0.w, b0.w);
            ureg[4][p] = pack2(a1.x, b1.x);
            ureg[5][p] = pack2(a1.y, b1.y);
            ureg[6][p] = pack2(a1.z, b1.z);
            ureg[7][p] = pack2(a1.w, b1.w);
        }
    }

    // zero h stage (h_0 = 0; staging skipped at t==0)
    for (int i = tid; i < 4 * KROW; i += 256) hs[i] = 0.f;

    // h read pointers (k offset ks*20; iter advances 4 floats = 1 u2)
    const ulonglong2* hp0 = (const ulonglong2*)(hs + 0 * KROW + ks * 20);
    const ulonglong2* hp1 = (const ulonglong2*)(hs + 1 * KROW + ks * 20);
    const ulonglong2* hp2 = (const ulonglong2*)(hs + 2 * KROW + ks * 20);
    const ulonglong2* hp3 = (const ulonglong2*)(hs + 3 * KROW + ks * 20);

    // staging: warp w handles producer w entirely (one flag, one 512B piece)
    const unsigned* sflag = &g_flag2[bgrp][wid][0];
    const int srow = lane >> 3;               // batch row 0..3
    const int scol = (lane & 7) * 4;          // col offset 0..28
    const int sj   = wid * 32 + scol;         // hidden col
    float* sdst = hs + srow * KROW + (sj >> 4) * 20 + (sj & 15);

    // gate-thread params (tid < 128): (bl 0..3, jj 0..31)
    const int bl = tid >> 5;
    const int jl = tid & 31;
    const int b  = bgrp * 4 + bl;
    const int j  = jgrp * 32 + jl;
    float c = 0.f;
    const float* xzp = g_xz + (size_t)b * TT * G4 + j;

    __syncthreads();   // hs ready

    for (int t = 0; t < TT; t++) {
        // xz prefetch (gate threads only; issued before any wait)
        float a0 = 0.f, a1 = 0.f, a2 = 0.f, a3 = 0.f;
        if (tid < 128) {
            const float* xr = xzp + (size_t)t * G4;
            a0 = __ldg(xr + 0 * HH);
            a1 = __ldg(xr + 1 * HH);
            a2 = __ldg(xr + 2 * HH);
            a3 = __ldg(xr + 3 * HH);
        }

        if (t > 0) {
            // ONE broadcast flag poll per warp, then fetch 512B piece
            while (ld_acq(sflag) < (unsigned)t) { }
            const float* src =
                g_hbuf[t & 1] + (bgrp * 4 + srow) * HH + wid * 32 + scol;
            float4 v = __ldcg((const float4*)(src));
            *(float4*)sdst = v;
        }
        __syncthreads();   // A: h staged

        // ---- main tile: 4b x 8gc x 16k, U from registers ----
        unsigned long long acc[32];
#pragma unroll
        for (int q = 0; q < 32; q++) acc[q] = 0ull;

#pragma unroll
        for (int iter = 0; iter < 4; iter++) {
            ulonglong2 h0 = hp0[iter];
            ulonglong2 h1 = hp1[iter];
            ulonglong2 h2 = hp2[iter];
            ulonglong2 h3 = hp3[iter];
#pragma unroll
            for (int t8 = 0; t8 < 8; t8++) {
                unsigned long long ux = ureg[t8][2 * iter];
                unsigned long long uy = ureg[t8][2 * iter + 1];
                acc[0 * 8 + t8] = ffma2(h0.x, ux, acc[0 * 8 + t8]);
                acc[0 * 8 + t8] = ffma2(h0.y, uy, acc[0 * 8 + t8]);
                acc[1 * 8 + t8] = ffma2(h1.x, ux, acc[1 * 8 + t8]);
                acc[1 * 8 + t8] = ffma2(h1.y, uy, acc[1 * 8 + t8]);
                acc[2 * 8 + t8] = ffma2(h2.x, ux, acc[2 * 8 + t8]);
                acc[2 * 8 + t8] = ffma2(h2.y, uy, acc[2 * 8 + t8]);
                acc[3 * 8 + t8] = ffma2(h3.x, ux, acc[3 * 8 + t8]);
                acc[3 * 8 + t8] = ffma2(h3.y, uy, acc[3 * 8 + t8]);
            }
        }

        // fold + write skewed partials: addr = (b*128 + gc)*17 + b*8 + ks
#pragma unroll
        for (int i = 0; i < 4; i++) {
            int base = (i * 128 + gcblk * 8) * 17 + i * 8 + ks;
#pragma unroll
            for (int t8 = 0; t8 < 8; t8++)
                part[base + t8 * 17] = sum2(acc[i * 8 + t8]);
        }
        __syncthreads();   // B: partials visible

        if (tid < 128) {
            float z[4];
#pragma unroll
            for (int g = 0; g < 4; g++) {
                int base = (bl * 128 + g * 32 + jl) * 17 + bl * 8;
                float s0 = part[base + 0] + part[base + 1];
                float s1 = part[base + 2] + part[base + 3];
                float s2 = part[base + 4] + part[base + 5];
                float s3 = part[base + 6] + part[base + 7];
                float s4 = part[base + 8] + part[base + 9];
                float s5 = part[base + 10] + part[base + 11];
                float s6 = part[base + 12] + part[base + 13];
                float s7 = part[base + 14] + part[base + 15];
                z[g] = ((s0 + s1) + (s2 + s3)) + ((s4 + s5) + (s6 + s7));
            }
            float z0 = a0 + z[0];
            float z1 = a1 + z[1];
            float z2 = a2 + z[2];
            float z3 = a3 + z[3];
            // gates (order i, f, g, o)
            float ig = sigm_ap(z0);
            float fg = sigm_ap(z1);
            float gg = tanh_ap(z2);
            float og = sigm_ap(z3);
            c = fmaf(fg, c, ig * gg);
            float hn = og * tanh_ap(c);
            __stcg(&g_hbuf[(t + 1) & 1][b * HH + j], hn);
            asm volatile("bar.sync 1, 128;" ::: "memory");
            if (tid == 0) st_rel(&g_flag2[bgrp][jgrp][0], (unsigned)(t + 1));
        }
    }
}

// ---------------------------------------------------------------------------
// Phase C: logits = h_T @ Wd + bd; softmax. One warp per batch row.
// Final h lives in g_hbuf[0] (512 steps -> buf (511+1)&1 == 0).
// ---------------------------------------------------------------------------
__global__ __launch_bounds__(32) void phaseC_kernel(
    const float* __restrict__ Wd, const float* __restrict__ bd,
    float* __restrict__ out)
{
    const int b = blockIdx.x;
    const int lane = threadIdx.x;
    const float* h = g_hbuf[0] + b * HH;

    float v = 0.f;
    if (lane < NCLS) {
#pragma unroll 8
        for (int k = 0; k < HH; k++)
            v = fmaf(h[k], Wd[k * NCLS + lane], v);
        v += bd[lane];
    }
    float m = (lane < NCLS) ? v : -1e30f;
#pragma unroll
    for (int o = 16; o; o >>= 1) m = fmaxf(m, __shfl_xor_sync(0xffffffffu, m, o));
    float e = (lane < NCLS) ? __expf(v - m) : 0.f;
    float s = e;
#pragma unroll
    for (int o = 16; o; o >>= 1) s += __shfl_xor_sync(0xffffffffu, s, o);
    if (lane < NCLS) out[b * NCLS + lane] = e / s;
}

// ---------------------------------------------------------------------------
extern "C" void kernel_launch(void* const* d_in, const int* in_sizes, int n_in,
                              void* d_out, int out_size)
{
    const int*   x    = (const int*)d_in[0];
    const float* emb  = (const float*)d_in[1];
    const float* W    = (const float*)d_in[2];
    const float* U    = (const float*)d_in[3];
    const float* bias = (const float*)d_in[4];
    const float* Wd   = (const float*)d_in[5];
    const float* bd   = (const float*)d_in[6];
    float* out = (float*)d_out;

    static void* flag_ptr = nullptr;
    static bool inited = false;
    if (!inited) {
        cudaGetSymbolAddress(&flag_ptr, g_flag2);
        cudaFuncSetAttribute(phaseB_kernel,
                             cudaFuncAttributeMaxDynamicSharedMemorySize, SMEM_B);
        inited = true;
    }

    // Reset cross-launch flag state (graph-capturable memset node)
    cudaMemsetAsync(flag_ptr, 0, sizeof(unsigned) * 16 * 8 * 32, 0);

    phaseA_kernel<<<dim3(8, 256), 256>>>(x, emb, W, bias);
    phaseB_kernel<<<dim3(8, 16), 256, SMEM_B>>>(U);
    phaseC_kernel<<<BB, 32>>>(Wd, bd, out);
}

// round 16
// speedup vs baseline: 2.7269x; 1.0113x over previous
#include <cuda_runtime.h>
#include <math.h>

#define BB 64        // batch
#define TT 512       // seq len
#define HH 256       // hidden
#define G4 1024      // 4*H
#define NCLS 20

// Scratch (static device globals — no runtime allocation)
__device__ float g_xz[(size_t)BB * TT * G4];   // 128 MB
__device__ float g_hbuf[2][BB * HH];
__device__ unsigned g_flag2[16][8][32];        // [bgrp][producer jgrp][line pad]

// ---------------------------------------------------------------------------
// helpers
// ---------------------------------------------------------------------------
__device__ __forceinline__ unsigned long long ffma2(unsigned long long a,
                                                    unsigned long long b,
                                                    unsigned long long c) {
    unsigned long long d;
    asm("fma.rn.f32x2 %0, %1, %2, %3;" : "=l"(d) : "l"(a), "l"(b), "l"(c));
    return d;
}
__device__ __forceinline__ unsigned long long pack2(float lo, float hi) {
    unsigned long long d;
    asm("mov.b64 %0, {%1, %2};" : "=l"(d) : "f"(lo), "f"(hi));
    return d;
}
__device__ __forceinline__ void unpack2(unsigned long long v, float& lo, float& hi) {
    asm("mov.b64 {%0, %1}, %2;" : "=f"(lo), "=f"(hi) : "l"(v));
}
__device__ __forceinline__ float sum2(unsigned long long v) {
    float lo, hi;
    asm("mov.b64 {%0, %1}, %2;" : "=f"(lo), "=f"(hi) : "l"(v));
    return lo + hi;
}
__device__ __forceinline__ unsigned ld_acq(const unsigned* p) {
    unsigned v;
    asm volatile("ld.acquire.gpu.global.b32 %0, [%1];" : "=r"(v) : "l"(p));
    return v;
}
__device__ __forceinline__ void st_rel(unsigned* p, unsigned v) {
    asm volatile("st.release.gpu.global.b32 [%0], %1;" :: "l"(p), "r"(v));
}
__device__ __forceinline__ float tanh_ap(float x) {
    float y;
    asm("tanh.approx.f32 %0, %1;" : "=f"(y) : "f"(x));
    return y;
}
__device__ __forceinline__ float sigm_ap(float x) {
    return fmaf(0.5f, tanh_ap(0.5f * x), 0.5f);
}

// ---------------------------------------------------------------------------
// Phase A: xz[b,t,:] = emb[x[b,t]] @ W + bias      (M=32768, K=256, N=1024)
// 128x128 tile, 256 threads, 8x8 micro-tile, PACKED f32x2 math:
// acc = 8 rows x 4 col-pair ulls; 32 ffma2 per k (vs 64 FFMA).
// ---------------------------------------------------------------------------
__global__ __launch_bounds__(256) void phaseA_kernel(
    const int* __restrict__ x, const float* __restrict__ emb,
    const float* __restrict__ W, const float* __restrict__ bias)
{
    __shared__ float As[16][136];
    __shared__ float Bs[16][136];
    __shared__ int ridx[128];

    const int tid = threadIdx.x;
    const int bx = blockIdx.x;   // 0..7
    const int by = blockIdx.y;   // 0..255

    if (tid < 128) ridx[tid] = x[by * 128 + tid];
    __syncthreads();

    const int tx = tid & 15;
    const int ty = tid >> 4;

    unsigned long long acc2[8][4];
#pragma unroll
    for (int i = 0; i < 8; i++)
#pragma unroll
        for (int j = 0; j < 4; j++) acc2[i][j] = 0ull;

    const int ar  = tid >> 1;
    const int akq = (tid & 1) << 3;
    const int bkk = tid >> 4;
    const int bc8 = (tid & 15) << 3;

    for (int k0 = 0; k0 < 256; k0 += 16) {
        {
            const float* ap = emb + (size_t)ridx[ar] * 256 + k0 + akq;
            float4 va = *(const float4*)(ap);
            float4 vb = *(const float4*)(ap + 4);
            As[akq + 0][ar] = va.x; As[akq + 1][ar] = va.y;
            As[akq + 2][ar] = va.z; As[akq + 3][ar] = va.w;
            As[akq + 4][ar] = vb.x; As[akq + 5][ar] = vb.y;
            As[akq + 6][ar] = vb.z; As[akq + 7][ar] = vb.w;
            const float* bp = W + (size_t)(k0 + bkk) * G4 + bx * 128 + bc8;
            *(float4*)&Bs[bkk][bc8]     = *(const float4*)(bp);
            *(float4*)&Bs[bkk][bc8 + 4] = *(const float4*)(bp + 4);
        }
        __syncthreads();
#pragma unroll
        for (int k = 0; k < 16; k++) {
            float4 a0 = *(const float4*)&As[k][ty << 3];
            float4 a1 = *(const float4*)&As[k][(ty << 3) + 4];
            // B pair-packed: 4 ulls = 8 consecutive cols (16B-aligned)
            ulonglong2 bb0 = *(const ulonglong2*)&Bs[k][tx << 3];
            ulonglong2 bb1 = *(const ulonglong2*)&Bs[k][(tx << 3) + 4];
            float a[8] = {a0.x, a0.y, a0.z, a0.w, a1.x, a1.y, a1.z, a1.w};
#pragma unroll
            for (int i = 0; i < 8; i++) {
                unsigned long long ad = pack2(a[i], a[i]);
                acc2[i][0] = ffma2(ad, bb0.x, acc2[i][0]);
                acc2[i][1] = ffma2(ad, bb0.y, acc2[i][1]);
                acc2[i][2] = ffma2(ad, bb1.x, acc2[i][2]);
                acc2[i][3] = ffma2(ad, bb1.y, acc2[i][3]);
            }
        }
        __syncthreads();
    }

    const int colbase = bx * 128 + (tx << 3);
    float4 bv0 = *(const float4*)(bias + colbase);
    float4 bv1 = *(const float4*)(bias + colbase + 4);
#pragma unroll
    for (int i = 0; i < 8; i++) {
        int row = by * 128 + (ty << 3) + i;
        float o0, o1, o2, o3, o4, o5, o6, o7;
        unpack2(acc2[i][0], o0, o1);
        unpack2(acc2[i][1], o2, o3);
        unpack2(acc2[i][2], o4, o5);
        unpack2(acc2[i][3], o6, o7);
        float4 w0 = make_float4(o0 + bv0.x, o1 + bv0.y, o2 + bv0.z, o3 + bv0.w);
        float4 w1 = make_float4(o4 + bv1.x, o5 + bv1.y, o6 + bv1.z, o7 + bv1.w);
        float* op = g_xz + (size_t)row * G4 + colbase;
        *(float4*)(op)     = w0;
        *(float4*)(op + 4) = w1;
    }
}

// ---------------------------------------------------------------------------
// Phase B: 512 LSTM steps, 128 CTAs = 8 jgrp x 16 bgrp. U in REGISTERS
// (8gc x 16k per thread as 64 packed ulls, loaded once). Hot loop reads only
// h from smem. Staging: warp w handles producer w (one flag poll + 512B
// piece). Skewed 16-way k-combine; gates by threads 0-127.
// (byte-identical to Round-15 winner)
// ---------------------------------------------------------------------------
#define KROW 320                     // 16 k-blocks * 20 floats (bank-optimal)
#define HS_OFF 0                     // [4][320]
#define PART_OFF (4 * KROW)          // skewed scratch
#define SMEM_FLOATS (PART_OFF + 8736)
#define SMEM_B (SMEM_FLOATS * 4)

extern __shared__ float sdyn[];

__global__ __launch_bounds__(256, 1) void phaseB_kernel(const float* __restrict__ U)
{
    float* hs   = sdyn + HS_OFF;
    float* part = sdyn + PART_OFF;

    const int tid  = threadIdx.x;      // 256
    const int jgrp = blockIdx.x;       // 0..7   (col group: 32 hidden cols)
    const int bgrp = blockIdx.y;       // 0..15  (4 batches)

    const int ks    = tid & 15;        // k split 0..15 (16 k each)
    const int gcblk = tid >> 4;        // 0..15 (8 gate-cols each)

    const int wid  = tid >> 5;         // 0..7
    const int lane = tid & 31;

    // ---- load this thread's U tile into registers (one-time) ----
    unsigned long long ureg[8][8];     // [t8][k-pair p], k = ks*16 + 2p
    {
        const int gc0  = gcblk * 8;
        const int colb = (gc0 >> 5) * HH + jgrp * 32 + (gc0 & 31);
#pragma unroll
        for (int p = 0; p < 8; p++) {
            const float* r0 = U + (size_t)(ks * 16 + 2 * p) * G4 + colb;
            const float* r1 = r0 + G4;
            float4 a0 = *(const float4*)(r0);
            float4 a1 = *(const float4*)(r0 + 4);
            float4 b0 = *(const float4*)(r1);
            float4 b1 = *(const float4*)(r1 + 4);
            ureg[0][p] = pack2(a0.x, b0.x);
            ureg[1][p] = pack2(a0.y, b0.y);
            ureg[2][p] = pack2(a0.z, b0.z);
            ureg[3][p] = pack2(a0.w, b0.w);
            ureg[4][p] = pack2(a1.x, b1.x);
            ureg[5][p] = pack2(a1.y, b1.y);
            ureg[6][p] = pack2(a1.z, b1.z);
            ureg[7][p] = pack2(a1.w, b1.w);
        }
    }

    // zero h stage (h_0 = 0; staging skipped at t==0)
    for (int i = tid; i < 4 * KROW; i += 256) hs[i] = 0.f;

    // h read pointers (k offset ks*20; iter advances 4 floats = 1 u2)
    const ulonglong2* hp0 = (const ulonglong2*)(hs + 0 * KROW + ks * 20);
    const ulonglong2* hp1 = (const ulonglong2*)(hs + 1 * KROW + ks * 20);
    const ulonglong2* hp2 = (const ulonglong2*)(hs + 2 * KROW + ks * 20);
    const ulonglong2* hp3 = (const ulonglong2*)(hs + 3 * KROW + ks * 20);

    // staging: warp w handles producer w entirely (one flag, one 512B piece)
    const unsigned* sflag = &g_flag2[bgrp][wid][0];
    const int srow = lane >> 3;               // batch row 0..3
    const int scol = (lane & 7) * 4;          // col offset 0..28
    const int sj   = wid * 32 + scol;         // hidden col
    float* sdst = hs + srow * KROW + (sj >> 4) * 20 + (sj & 15);

    // gate-thread params (tid < 128): (bl 0..3, jj 0..31)
    const int bl = tid >> 5;
    const int jl = tid & 31;
    const int b  = bgrp * 4 + bl;
    const int j  = jgrp * 32 + jl;
    float c = 0.f;
    const float* xzp = g_xz + (size_t)b * TT * G4 + j;

    __syncthreads();   // hs ready

    for (int t = 0; t < TT; t++) {
        // xz prefetch (gate threads only; issued before any wait)
        float a0 = 0.f, a1 = 0.f, a2 = 0.f, a3 = 0.f;
        if (tid < 128) {
            const float* xr = xzp + (size_t)t * G4;
            a0 = __ldg(xr + 0 * HH);
            a1 = __ldg(xr + 1 * HH);
            a2 = __ldg(xr + 2 * HH);
            a3 = __ldg(xr + 3 * HH);
        }

        if (t > 0) {
            // ONE broadcast flag poll per warp, then fetch 512B piece
            while (ld_acq(sflag) < (unsigned)t) { }
            const float* src =
                g_hbuf[t & 1] + (bgrp * 4 + srow) * HH + wid * 32 + scol;
            float4 v = __ldcg((const float4*)(src));
            *(float4*)sdst = v;
        }
        __syncthreads();   // A: h staged

        // ---- main tile: 4b x 8gc x 16k, U from registers ----
        unsigned long long acc[32];
#pragma unroll
        for (int q = 0; q < 32; q++) acc[q] = 0ull;

#pragma unroll
        for (int iter = 0; iter < 4; iter++) {
            ulonglong2 h0 = hp0[iter];
            ulonglong2 h1 = hp1[iter];
            ulonglong2 h2 = hp2[iter];
            ulonglong2 h3 = hp3[iter];
#pragma unroll
            for (int t8 = 0; t8 < 8; t8++) {
                unsigned long long ux = ureg[t8][2 * iter];
                unsigned long long uy = ureg[t8][2 * iter + 1];
                acc[0 * 8 + t8] = ffma2(h0.x, ux, acc[0 * 8 + t8]);
                acc[0 * 8 + t8] = ffma2(h0.y, uy, acc[0 * 8 + t8]);
                acc[1 * 8 + t8] = ffma2(h1.x, ux, acc[1 * 8 + t8]);
                acc[1 * 8 + t8] = ffma2(h1.y, uy, acc[1 * 8 + t8]);
                acc[2 * 8 + t8] = ffma2(h2.x, ux, acc[2 * 8 + t8]);
                acc[2 * 8 + t8] = ffma2(h2.y, uy, acc[2 * 8 + t8]);
                acc[3 * 8 + t8] = ffma2(h3.x, ux, acc[3 * 8 + t8]);
                acc[3 * 8 + t8] = ffma2(h3.y, uy, acc[3 * 8 + t8]);
            }
        }

        // fold + write skewed partials: addr = (b*128 + gc)*17 + b*8 + ks
#pragma unroll
        for (int i = 0; i < 4; i++) {
            int base = (i * 128 + gcblk * 8) * 17 + i * 8 + ks;
#pragma unroll
            for (int t8 = 0; t8 < 8; t8++)
                part[base + t8 * 17] = sum2(acc[i * 8 + t8]);
        }
        __syncthreads();   // B: partials visible

        if (tid < 128) {
            float z[4];
#pragma unroll
            for (int g = 0; g < 4; g++) {
                int base = (bl * 128 + g * 32 + jl) * 17 + bl * 8;
                float s0 = part[base + 0] + part[base + 1];
                float s1 = part[base + 2] + part[base + 3];
                float s2 = part[base + 4] + part[base + 5];
                float s3 = part[base + 6] + part[base + 7];
                float s4 = part[base + 8] + part[base + 9];
                float s5 = part[base + 10] + part[base + 11];
                float s6 = part[base + 12] + part[base + 13];
                float s7 = part[base + 14] + part[base + 15];
                z[g] = ((s0 + s1) + (s2 + s3)) + ((s4 + s5) + (s6 + s7));
            }
            float z0 = a0 + z[0];
            float z1 = a1 + z[1];
            float z2 = a2 + z[2];
            float z3 = a3 + z[3];
            // gates (order i, f, g, o)
            float ig = sigm_ap(z0);
            float fg = sigm_ap(z1);
            float gg = tanh_ap(z2);
            float og = sigm_ap(z3);
            c = fmaf(fg, c, ig * gg);
            float hn = og * tanh_ap(c);
            __stcg(&g_hbuf[(t + 1) & 1][b * HH + j], hn);
            asm volatile("bar.sync 1, 128;" ::: "memory");
            if (tid == 0) st_rel(&g_flag2[bgrp][jgrp][0], (unsigned)(t + 1));
        }
    }
}

// ---------------------------------------------------------------------------
// Phase C: logits = h_T @ Wd + bd; softmax. One warp per batch row.
// Final h lives in g_hbuf[0] (512 steps -> buf (511+1)&1 == 0).
// ---------------------------------------------------------------------------
__global__ __launch_bounds__(32) void phaseC_kernel(
    const float* __restrict__ Wd, const float* __restrict__ bd,
    float* __restrict__ out)
{
    const int b = blockIdx.x;
    const int lane = threadIdx.x;
    const float* h = g_hbuf[0] + b * HH;

    float v = 0.f;
    if (lane < NCLS) {
#pragma unroll 8
        for (int k = 0; k < HH; k++)
            v = fmaf(h[k], Wd[k * NCLS + lane], v);
        v += bd[lane];
    }
    float m = (lane < NCLS) ? v : -1e30f;
#pragma unroll
    for (int o = 16; o; o >>= 1) m = fmaxf(m, __shfl_xor_sync(0xffffffffu, m, o));
    float e = (lane < NCLS) ? __expf(v - m) : 0.f;
    float s = e;
#pragma unroll
    for (int o = 16; o; o >>= 1) s += __shfl_xor_sync(0xffffffffu, s, o);
    if (lane < NCLS) out[b * NCLS + lane] = e / s;
}

// ---------------------------------------------------------------------------
extern "C" void kernel_launch(void* const* d_in, const int* in_sizes, int n_in,
                              void* d_out, int out_size)
{
    const int*   x    = (const int*)d_in[0];
    const float* emb  = (const float*)d_in[1];
    const float* W    = (const float*)d_in[2];
    const float* U    = (const float*)d_in[3];
    const float* bias = (const float*)d_in[4];
    const float* Wd   = (const float*)d_in[5];
    const float* bd   = (const float*)d_in[6];
    float* out = (float*)d_out;

    static void* flag_ptr = nullptr;
    static bool inited = false;
    if (!inited) {
        cudaGetSymbolAddress(&flag_ptr, g_flag2);
        cudaFuncSetAttribute(phaseB_kernel,
                             cudaFuncAttributeMaxDynamicSharedMemorySize, SMEM_B);
        inited = true;
    }

    // Reset cross-launch flag state (graph-capturable memset node)
    cudaMemsetAsync(flag_ptr, 0, sizeof(unsigned) * 16 * 8 * 32, 0);

    phaseA_kernel<<<dim3(8, 256), 256>>>(x, emb, W, bias);
    phaseB_kernel<<<dim3(8, 16), 256, SMEM_B>>>(U);
    phaseC_kernel<<<BB, 32>>>(Wd, bd, out);
}